// round 1
// baseline (speedup 1.0000x reference)
#include <cuda_runtime.h>
#include <cstdint>

// Shapes (fixed by setup_inputs):
// x: (2, 96, 32, 64, 64) f32 ; gamma/beta: (768,) ; w_red: (768, 192)
// out: (2, 192, 16, 32, 32) f32
#define D2 16
#define H2 32
#define W2 32
#define NTOK 32768           // 2*16*32*32 tokens
#define KDIM 768
#define NOUT 192

// x strides (floats)
#define SH 64
#define SD 4096              // 64*64
#define SC 131072            // 32*64*64
#define SB 12582912          // 96*SC

// out strides (floats)
#define OSN 16384            // 16*32*32
#define OSB 3145728          // 192*OSN

__device__ float g_mean[NTOK];
__device__ float g_rstd[NTOK];

__device__ __forceinline__ float to_tf32(float a) {
    unsigned u;
    asm("cvt.rna.tf32.f32 %0, %1;" : "=r"(u) : "f"(a));
    return __uint_as_float(u);
}

__device__ __forceinline__ void mma_tf32(float c[4], const float a[4], const float b[2]) {
    asm volatile(
        "mma.sync.aligned.m16n8k8.row.col.f32.tf32.tf32.f32 "
        "{%0,%1,%2,%3}, {%4,%5,%6,%7}, {%8,%9}, {%0,%1,%2,%3};"
        : "+f"(c[0]), "+f"(c[1]), "+f"(c[2]), "+f"(c[3])
        : "r"(__float_as_uint(a[0])), "r"(__float_as_uint(a[1])),
          "r"(__float_as_uint(a[2])), "r"(__float_as_uint(a[3])),
          "r"(__float_as_uint(b[0])), "r"(__float_as_uint(b[1])));
}

// ---------------- Kernel 1: per-token LayerNorm statistics ----------------
// One warp per (b,dz,hy) row; lane = wx. float2 at w=2*wx covers w0=0 and w0=1,
// both belonging to token (b,dz,hy,wx) -> fully coalesced 256B accesses.
__global__ __launch_bounds__(128) void stats_kernel(const float* __restrict__ x) {
    int row = blockIdx.x * 4 + (threadIdx.x >> 5);   // 0..1023
    int lane = threadIdx.x & 31;                      // wx
    int b = row >> 9;
    int dz = (row >> 5) & 15;
    int hy = row & 31;
    const float* base = x + (size_t)b * SB + (2 * dz) * SD + (2 * hy) * SH + 2 * lane;
    float s = 0.f, ss = 0.f;
    #pragma unroll 1
    for (int j = 0; j < 4; ++j) {                     // (d0,h0) pairs
        const float* p = base + (j >> 1) * SD + (j & 1) * SH;
        #pragma unroll 4
        for (int c = 0; c < 96; ++c) {
            float2 v = *reinterpret_cast<const float2*>(p + (size_t)c * SC);
            s  += v.x + v.y;
            ss += v.x * v.x + v.y * v.y;
        }
    }
    float mu  = s * (1.0f / 768.0f);
    float var = ss * (1.0f / 768.0f) - mu * mu;
    int t = row * 32 + lane;
    g_mean[t] = mu;
    g_rstd[t] = rsqrtf(var + 1e-5f);
}

// ---------------- Kernel 2: fused gather + LN + GEMM (tf32 mma.sync) -------
// CTA tile: M=128 tokens (4 (b,dz,hy) rows x 32 wx) x N=192, K looped.
// K super-chunks of 64: octant pair (2j,2j+1) share (d0,h0) so one float2
// global load provides two K entries of the same token.
#define PA 136   // A smem row pad: [64 k][PA m]; bank = 8*tig+g -> conflict-free
#define PB 200   // B smem row pad: [64 k][PB n]; bank = 8*tig+g -> conflict-free
#define SMEM_BYTES ((64 * PA + 64 * PB) * 4)   // 86016

__global__ __launch_bounds__(256, 1) void gemm_kernel(
    const float* __restrict__ x, const float* __restrict__ gamma,
    const float* __restrict__ beta, const float* __restrict__ w,
    float* __restrict__ out)
{
    extern __shared__ float smem[];
    float* As = smem;                 // [64][PA]  (k-major, M inner)
    float* Bs = smem + 64 * PA;       // [64][PB]  (k-major, N inner)

    const int tid  = threadIdx.x;
    const int lane = tid & 31;
    const int warp = tid >> 5;
    const int g    = lane >> 2;       // groupID
    const int tig  = lane & 3;        // thread-in-group
    const int warpRow = warp >> 2;    // 0..1 -> 64 M rows each
    const int warpCol = warp & 3;     // 0..3 -> 48 N cols each
    const int rbase = blockIdx.x * 4; // first (b,dz,hy) row of this CTA

    float acc[4][6][4];
    #pragma unroll
    for (int i = 0; i < 4; ++i)
        #pragma unroll
        for (int j = 0; j < 6; ++j)
            #pragma unroll
            for (int k = 0; k < 4; ++k) acc[i][j][k] = 0.f;

    for (int sc = 0; sc < 12; ++sc) {
        const int oj  = sc / 3;             // octant pair index 0..3
        const int cb  = (sc % 3) * 32;      // channel sub-block
        const int d0  = oj >> 1, h0 = oj & 1;
        const int kb0 = (2 * oj) * 96 + cb; // global k of kk=0

        __syncthreads();   // previous compute phase done reading smem

        // ---- load B chunk: rows kk=0..63 -> w_red[kglob][0..191]
        #pragma unroll
        for (int it = 0; it < 12; ++it) {
            int idx = tid + it * 256;          // 0..3071
            int row = idx / 48;
            int c4  = idx % 48;
            int kg  = kb0 + row + ((row & 32) ? 64 : 0); // kk>=32 -> +96-32
            float4 v = *reinterpret_cast<const float4*>(w + (size_t)kg * NOUT + c4 * 4);
            v.x = to_tf32(v.x); v.y = to_tf32(v.y);
            v.z = to_tf32(v.z); v.w = to_tf32(v.w);
            *reinterpret_cast<float4*>(&Bs[row * PB + c4 * 4]) = v;
        }

        // ---- load A chunk: gather + LayerNorm, 128 m x 64 k via float2
        #pragma unroll
        for (int it = 0; it < 16; ++it) {
            int idx = tid + it * 256;          // 0..4095
            int wx  = idx & 31;
            int tmp = idx >> 5;
            int cc  = tmp & 31;                // channel within sub-block
            int rowLocal = tmp >> 5;           // 0..3
            int r  = rbase + rowLocal;
            int b  = r >> 9;
            int dz = (r >> 5) & 15;
            int hy = r & 31;
            const float* src = x + (size_t)b * SB + (size_t)(cb + cc) * SC
                             + (2 * dz + d0) * SD + (2 * hy + h0) * SH + 2 * wx;
            float2 v = *reinterpret_cast<const float2*>(src);
            int t = r * 32 + wx;
            float mu = g_mean[t], rs = g_rstd[t];
            int k0 = kb0 + cc, k1 = k0 + 96;
            float a0 = (v.x - mu) * rs * __ldg(gamma + k0) + __ldg(beta + k0);
            float a1 = (v.y - mu) * rs * __ldg(gamma + k1) + __ldg(beta + k1);
            int m = rowLocal * 32 + wx;
            As[cc * PA + m]        = to_tf32(a0);
            As[(cc + 32) * PA + m] = to_tf32(a1);
        }

        __syncthreads();

        // ---- compute: 8 k-steps of 8
        const float* Ab = As + warpRow * 64;
        const float* Bb = Bs + warpCol * 48;
        #pragma unroll
        for (int ks = 0; ks < 8; ++ks) {
            int k0 = ks * 8;
            float af[4][4];
            #pragma unroll
            for (int mi = 0; mi < 4; ++mi) {
                const float* p = Ab + (k0 + tig) * PA + mi * 16 + g;
                af[mi][0] = p[0];
                af[mi][1] = p[8];
                af[mi][2] = p[4 * PA];
                af[mi][3] = p[4 * PA + 8];
            }
            float bf[6][2];
            #pragma unroll
            for (int ni = 0; ni < 6; ++ni) {
                const float* q = Bb + (k0 + tig) * PB + ni * 8 + g;
                bf[ni][0] = q[0];
                bf[ni][1] = q[4 * PB];
            }
            #pragma unroll
            for (int mi = 0; mi < 4; ++mi)
                #pragma unroll
                for (int ni = 0; ni < 6; ++ni)
                    mma_tf32(acc[mi][ni], af[mi], bf[ni]);
        }
    }

    // ---- epilogue: scatter to (B,192,16,32,32)
    const int mwbase = warpRow * 64;
    #pragma unroll
    for (int mi = 0; mi < 4; ++mi) {
        #pragma unroll
        for (int rr = 0; rr < 2; ++rr) {
            int m  = mwbase + mi * 16 + rr * 8 + g;
            int rowLocal = m >> 5;
            int wx = m & 31;
            int r  = rbase + rowLocal;
            int b  = r >> 9;
            int dz = (r >> 5) & 15;
            int hy = r & 31;
            size_t obase = (size_t)b * OSB + dz * 1024 + hy * 32 + wx;
            #pragma unroll
            for (int ni = 0; ni < 6; ++ni) {
                int n = warpCol * 48 + ni * 8 + tig * 2;
                out[obase + (size_t)n * OSN]       = acc[mi][ni][rr * 2];
                out[obase + (size_t)(n + 1) * OSN] = acc[mi][ni][rr * 2 + 1];
            }
        }
    }
}

extern "C" void kernel_launch(void* const* d_in, const int* in_sizes, int n_in,
                              void* d_out, int out_size) {
    const float* x     = (const float*)d_in[0];
    const float* gamma = (const float*)d_in[1];
    const float* beta  = (const float*)d_in[2];
    const float* w     = (const float*)d_in[3];
    float* out = (float*)d_out;

    stats_kernel<<<256, 128>>>(x);

    cudaFuncSetAttribute(gemm_kernel,
                         cudaFuncAttributeMaxDynamicSharedMemorySize, SMEM_BYTES);
    gemm_kernel<<<256, 256, SMEM_BYTES>>>(x, gamma, beta, w, out);
}

// round 3
// speedup vs baseline: 1.6705x; 1.6705x over previous
#include <cuda_runtime.h>
#include <cstdint>

// x: (2, 96, 32, 64, 64) f32 ; gamma/beta: (768,) ; w_red: (768, 192)
// out: (2, 192, 16, 32, 32) f32
#define KDIM 768
#define NOUT 192

// x strides (floats)
#define SH 64
#define SD 4096
#define SC 131072
#define SB 12582912
// out strides (floats)
#define OSN 16384
#define OSB 3145728

// Precomputed: W2 = tf32(gamma_k * W[k][n]); G[n] = sum_k W2; Bt[n] = sum_k beta_k*W
__device__ float W2buf[KDIM * NOUT];
__device__ float Gbuf[NOUT];
__device__ float Btbuf[NOUT];

__device__ __forceinline__ float to_tf32(float a) {
    unsigned u;
    asm("cvt.rna.tf32.f32 %0, %1;" : "=r"(u) : "f"(a));
    return __uint_as_float(u);
}

__device__ __forceinline__ void mma_tf32(float c[4], const float a[4], const float b[2]) {
    asm volatile(
        "mma.sync.aligned.m16n8k8.row.col.f32.tf32.tf32.f32 "
        "{%0,%1,%2,%3}, {%4,%5,%6,%7}, {%8,%9}, {%0,%1,%2,%3};"
        : "+f"(c[0]), "+f"(c[1]), "+f"(c[2]), "+f"(c[3])
        : "r"(__float_as_uint(a[0])), "r"(__float_as_uint(a[1])),
          "r"(__float_as_uint(a[2])), "r"(__float_as_uint(a[3])),
          "r"(__float_as_uint(b[0])), "r"(__float_as_uint(b[1])));
}

__device__ __forceinline__ void cpa8(uint32_t d, const void* s) {
    asm volatile("cp.async.ca.shared.global [%0], [%1], 8;" :: "r"(d), "l"(s));
}
__device__ __forceinline__ void cpa16(uint32_t d, const void* s) {
    asm volatile("cp.async.cg.shared.global [%0], [%1], 16;" :: "r"(d), "l"(s));
}
__device__ __forceinline__ void cp_commit() {
    asm volatile("cp.async.commit_group;");
}
__device__ __forceinline__ void cp_wait1() {
    asm volatile("cp.async.wait_group 1;");
}

// ---------------- prep kernels (tiny) ----------------
__global__ __launch_bounds__(256) void prep_w(const float* __restrict__ gamma,
                                              const float* __restrict__ w) {
    int idx = blockIdx.x * 256 + threadIdx.x;          // float4 index, 0..36863
    if (idx >= KDIM * NOUT / 4) return;
    int k = idx / 48, n4 = idx % 48;
    float gk = __ldg(&gamma[k]);
    float4 v = *reinterpret_cast<const float4*>(w + (size_t)k * NOUT + n4 * 4);
    v.x = to_tf32(v.x * gk); v.y = to_tf32(v.y * gk);
    v.z = to_tf32(v.z * gk); v.w = to_tf32(v.w * gk);
    *reinterpret_cast<float4*>(W2buf + (size_t)k * NOUT + n4 * 4) = v;
}

__global__ __launch_bounds__(256) void prep_gb(const float* __restrict__ beta,
                                               const float* __restrict__ w) {
    __shared__ float sg[256], sb[256];
    int n = blockIdx.x, t = threadIdx.x;
    float s = 0.f, bs = 0.f;
    for (int k = t; k < KDIM; k += 256) {
        s  += W2buf[(size_t)k * NOUT + n];
        bs += __ldg(&beta[k]) * __ldg(&w[(size_t)k * NOUT + n]);
    }
    sg[t] = s; sb[t] = bs; __syncthreads();
    for (int off = 128; off; off >>= 1) {
        if (t < off) { sg[t] += sg[t + off]; sb[t] += sb[t + off]; }
        __syncthreads();
    }
    if (t == 0) { Gbuf[n] = sg[0]; Btbuf[n] = sb[0]; }
}

// ---------------- fused single-pass kernel ----------------
// CTA: M=128 tokens x N=192, K in 12 superchunks of 64 (32 cc x 2 octant-pair).
// A smem: [32 cc][128 m][2 p], row stride ARS=264 floats (conflict-free LDS.64).
// B smem: [64 rows][192 n], row stride BRS=200. Double buffered, cp.async.
#define ARS 264
#define BRS 200
#define A_FLOATS (32 * ARS)                 // 8448
#define BUF_FLOATS (A_FLOATS + 64 * BRS)    // 21248
#define SMEM_BYTES (2 * BUF_FLOATS * 4)     // 169984

__device__ __forceinline__ void issue_chunk(int sc, uint32_t a_u, uint32_t b_u,
                                            const float* __restrict__ x,
                                            int tid, int rbase) {
    const int oj = sc / 3;
    const int cb = (sc % 3) * 32;
    const int d0 = oj >> 1, h0 = oj & 1;
    const int kb0 = oj * 192 + cb;
    // A: 32cc x 128m float2 gathers (4096 8B copies / 256 thr = 16 each)
    #pragma unroll
    for (int it = 0; it < 16; ++it) {
        int idx = tid + it * 256;
        int wx = idx & 31;
        int tmp = idx >> 5;
        int cc = tmp & 31;
        int rowLocal = tmp >> 5;
        int r = rbase + rowLocal;
        int b = r >> 9, dz = (r >> 5) & 15, hy = r & 31;
        const float* src = x + (size_t)b * SB + (size_t)(cb + cc) * SC
                         + (2 * dz + d0) * SD + (2 * hy + h0) * SH + 2 * wx;
        uint32_t dst = a_u + (cc * ARS + (rowLocal * 32 + wx) * 2) * 4;
        cpa8(dst, src);
    }
    // B: 64 rows x 48 float4 from W2buf (3072 / 256 = 12 each)
    #pragma unroll
    for (int it = 0; it < 12; ++it) {
        int idx = tid + it * 256;
        int rB = idx / 48, c4 = idx % 48;
        int kg = kb0 + ((rB >> 3) << 2) + (rB & 3) + 96 * ((rB >> 2) & 1);
        const float* src = W2buf + (size_t)kg * NOUT + c4 * 4;
        uint32_t dst = b_u + (rB * BRS + c4 * 4) * 4;
        cpa16(dst, src);
    }
}

__global__ __launch_bounds__(256, 1) void gemm_kernel(
    const float* __restrict__ x, float* __restrict__ out)
{
    extern __shared__ float smem[];
    uint32_t s_u = (uint32_t)__cvta_generic_to_shared(smem);

    const int tid = threadIdx.x;
    const int lane = tid & 31;
    const int warp = tid >> 5;
    const int g = lane >> 2;
    const int tig = lane & 3;
    const int warpRow = warp >> 2;          // 0..1 (64 m each)
    const int warpCol = warp & 3;           // 0..3 (48 n each)
    const int rbase = blockIdx.x * 4;
    const bool duty = (warp == 0) || (warp == 7);   // stats duty, distinct SMSPs

    float acc[4][6][4];
    #pragma unroll
    for (int i = 0; i < 4; ++i)
        #pragma unroll
        for (int j = 0; j < 6; ++j)
            #pragma unroll
            for (int k = 0; k < 4; ++k) acc[i][j][k] = 0.f;

    float sac[4][2], ssac[4][2];
    #pragma unroll
    for (int i = 0; i < 4; ++i) { sac[i][0] = sac[i][1] = 0.f; ssac[i][0] = ssac[i][1] = 0.f; }

    // prologue: fill both buffers
    issue_chunk(0, s_u, s_u + A_FLOATS * 4, x, tid, rbase);
    cp_commit();
    issue_chunk(1, s_u + BUF_FLOATS * 4, s_u + (BUF_FLOATS + A_FLOATS) * 4, x, tid, rbase);
    cp_commit();

    for (int sc = 0; sc < 12; ++sc) {
        cp_wait1();
        __syncthreads();

        const float* As = smem + (sc & 1) * BUF_FLOATS;
        const float* Bs = As + A_FLOATS;
        const float* Ab = As + (warpRow * 64) * 2;
        const float* Bb = Bs + warpCol * 48;

        #pragma unroll
        for (int ks = 0; ks < 8; ++ks) {
            float af[4][4];
            #pragma unroll
            for (int mi = 0; mi < 4; ++mi) {
                const float2 v0 = *reinterpret_cast<const float2*>(
                    Ab + (ks * 4 + tig) * ARS + (mi * 16 + g) * 2);
                const float2 v1 = *reinterpret_cast<const float2*>(
                    Ab + (ks * 4 + tig) * ARS + (mi * 16 + 8 + g) * 2);
                af[mi][0] = v0.x; af[mi][2] = v0.y;     // k=tig, k=tig+4 (p pair)
                af[mi][1] = v1.x; af[mi][3] = v1.y;
            }
            if (duty) {
                #pragma unroll
                for (int mi = 0; mi < 4; ++mi) {
                    sac[mi][0]  += af[mi][0] + af[mi][2];
                    ssac[mi][0] += af[mi][0] * af[mi][0] + af[mi][2] * af[mi][2];
                    sac[mi][1]  += af[mi][1] + af[mi][3];
                    ssac[mi][1] += af[mi][1] * af[mi][1] + af[mi][3] * af[mi][3];
                }
            }
            float bf[6][2];
            #pragma unroll
            for (int ni = 0; ni < 6; ++ni) {
                bf[ni][0] = Bb[(ks * 8 + tig) * BRS + ni * 8 + g];
                bf[ni][1] = Bb[(ks * 8 + tig + 4) * BRS + ni * 8 + g];
            }
            #pragma unroll
            for (int mi = 0; mi < 4; ++mi)
                #pragma unroll
                for (int ni = 0; ni < 6; ++ni)
                    mma_tf32(acc[mi][ni], af[mi], bf[ni]);
        }

        __syncthreads();
        if (sc + 2 < 12) {
            uint32_t base = s_u + (sc & 1) * BUF_FLOATS * 4;
            issue_chunk(sc + 2, base, base + A_FLOATS * 4, x, tid, rbase);
        }
        cp_commit();
    }

    // ---- finalize LayerNorm stats (duty warps cover all 128 tokens)
    float* mu_s = smem;          // reuse buffer 0 (all compute done)
    float* rs_s = smem + 128;
    if (duty) {
        #pragma unroll
        for (int mi = 0; mi < 4; ++mi) {
            #pragma unroll
            for (int r = 0; r < 2; ++r) {
                float s = sac[mi][r], q = ssac[mi][r];
                s += __shfl_xor_sync(0xffffffffu, s, 1);
                q += __shfl_xor_sync(0xffffffffu, q, 1);
                s += __shfl_xor_sync(0xffffffffu, s, 2);
                q += __shfl_xor_sync(0xffffffffu, q, 2);
                if (tig == 0) {
                    int m = warpRow * 64 + mi * 16 + r * 8 + g;
                    float mu = s * (1.0f / 768.0f);
                    float var = q * (1.0f / 768.0f) - mu * mu;
                    mu_s[m] = mu;
                    rs_s[m] = rsqrtf(var + 1e-5f);
                }
            }
        }
    }
    __syncthreads();

    // ---- epilogue: out = rs*(acc - mu*G) + Bt, scatter to (B,192,16,32,32)
    #pragma unroll
    for (int mi = 0; mi < 4; ++mi) {
        #pragma unroll
        for (int rr = 0; rr < 2; ++rr) {
            int m = warpRow * 64 + mi * 16 + rr * 8 + g;
            float mu = mu_s[m], rs = rs_s[m];
            int rowLocal = m >> 5;
            int wx = m & 31;
            int r = rbase + rowLocal;
            int b = r >> 9, dz = (r >> 5) & 15, hy = r & 31;
            size_t obase = (size_t)b * OSB + dz * 1024 + hy * 32 + wx;
            #pragma unroll
            for (int ni = 0; ni < 6; ++ni) {
                int n = warpCol * 48 + ni * 8 + tig * 2;
                float G0 = __ldg(&Gbuf[n]),     G1 = __ldg(&Gbuf[n + 1]);
                float B0 = __ldg(&Btbuf[n]),    B1 = __ldg(&Btbuf[n + 1]);
                out[obase + (size_t)n * OSN]       = rs * (acc[mi][ni][rr * 2]     - mu * G0) + B0;
                out[obase + (size_t)(n + 1) * OSN] = rs * (acc[mi][ni][rr * 2 + 1] - mu * G1) + B1;
            }
        }
    }
}

extern "C" void kernel_launch(void* const* d_in, const int* in_sizes, int n_in,
                              void* d_out, int out_size) {
    const float* x     = (const float*)d_in[0];
    const float* gamma = (const float*)d_in[1];
    const float* beta  = (const float*)d_in[2];
    const float* w     = (const float*)d_in[3];
    float* out = (float*)d_out;

    prep_w<<<144, 256>>>(gamma, w);
    prep_gb<<<192, 256>>>(beta, w);

    cudaFuncSetAttribute(gemm_kernel,
                         cudaFuncAttributeMaxDynamicSharedMemorySize, SMEM_BYTES);
    gemm_kernel<<<256, 256, SMEM_BYTES>>>(x, out);
}